// round 16
// baseline (speedup 1.0000x reference)
#include <cuda_runtime.h>
#include <cstdint>

#define D_DIM   2048
#define TOKENS  32768
#define T_TOK   4
#define NTILES  (TOKENS / T_TOK)     // 8192 exact
#define BLOCK   256                  // 8 warps: (role 0|1) x (d-quarter 0..3)
#define GRID    152
// score exchange: [parity 2][score 16][tok 4][quarter 4] floats = 2KB
#define SMEM_FLOATS (2 * 16 * 4 * 4)

__device__ __forceinline__ void ffma2(unsigned long long &acc,
                                      unsigned long long a,
                                      unsigned long long b) {
    asm("fma.rn.f32x2 %0, %1, %2, %0;" : "+l"(acc) : "l"(a), "l"(b));
}

// Load one 128-float block of this warp's quarter for T_TOK tokens.
#define LOADX(buf, xq, blk)                                                    \
    {                                                                          \
        _Pragma("unroll")                                                      \
        for (int t = 0; t < T_TOK; t++)                                        \
            buf[t] = *reinterpret_cast<const ulonglong2*>(                     \
                (xq) + (size_t)t * D_DIM + (blk) * 128);                       \
    }

// FMA one block against register-resident W: 8 rows x T_TOK tokens.
#define COMPW(buf, blk)                                                        \
    {                                                                          \
        _Pragma("unroll")                                                      \
        for (int r = 0; r < 8; r++) {                                          \
            _Pragma("unroll")                                                  \
            for (int t = 0; t < T_TOK; t++) {                                  \
                ffma2(acc[r][t], buf[t].x, Wr[r][blk].x);                      \
                ffma2(acc[r][t], buf[t].y, Wr[r][blk].y);                      \
            }                                                                  \
        }                                                                      \
    }

extern "C" __global__ void __launch_bounds__(BLOCK, 1)
router_kernel(const float* __restrict__ x,
              const float* __restrict__ W1,
              const float* __restrict__ W2,
              float* __restrict__ out)
{
    __shared__ float scx[SMEM_FLOATS];

    const int lane = threadIdx.x & 31;
    const int wid  = threadIdx.x >> 5;
    const int role = wid & 1;            // 0 = W1 (group) rows, 1 = W2 (expert) rows
    const int dq   = wid >> 1;           // d-quarter 0..3 (512 floats each)

    // ---- W lives in registers: 8 rows x 4 blocks x float4 per lane (128 regs).
    const float* Wbase = role ? W2 : W1;
    ulonglong2 Wr[8][4];
    #pragma unroll
    for (int r = 0; r < 8; r++)
        #pragma unroll
        for (int b = 0; b < 4; b++)
            Wr[r][b] = *reinterpret_cast<const ulonglong2*>(
                Wbase + r * D_DIM + dq * 512 + b * 128 + lane * 4);

    int tile = blockIdx.x;
    const float* xp = x + (size_t)tile * T_TOK * D_DIM + dq * 512 + lane * 4;

    // prime the x pipeline (blocks 0,1 of tile 0)
    ulonglong2 bA[T_TOK], bB[T_TOK];
    LOADX(bA, xp, 0);
    LOADX(bB, xp, 1);

    int par = 0;
    for (; tile < NTILES; tile += GRID, par ^= 1) {
        const int tok0 = tile * T_TOK;
        // next tile's x base (clamped; duplicate prefetch is harmless)
        const int ntile = (tile + GRID < NTILES) ? (tile + GRID) : tile;
        const float* xn = x + (size_t)ntile * T_TOK * D_DIM + dq * 512 + lane * 4;

        unsigned long long acc[8][T_TOK];
        #pragma unroll
        for (int r = 0; r < 8; r++)
            #pragma unroll
            for (int t = 0; t < T_TOK; t++)
                acc[r][t] = 0ull;

        COMPW(bA, 0); LOADX(bA, xp, 2);
        COMPW(bB, 1); LOADX(bB, xp, 3);
        COMPW(bA, 2); LOADX(bA, xn, 0);   // next-tile prefetch covers reduce phase
        COMPW(bB, 3); LOADX(bB, xn, 1);
        xp = xn;

        // Split-lane reduction over the 32 lanes (this warp's d-quarter):
        // pairs (rp, rp+4); lane t ends with row rp, lane 16+t with row rp+4.
        float lo[4], hi[4];
        #pragma unroll
        for (int rp = 0; rp < 4; rp++) {
            #pragma unroll
            for (int t = 0; t < T_TOK; t++) {
                float2 fa = *reinterpret_cast<float2*>(&acc[rp][t]);
                float2 fb = *reinterpret_cast<float2*>(&acc[rp + 4][t]);
                float a = fa.x + fa.y;
                float b = fb.x + fb.y;
                float ta = __shfl_xor_sync(0xffffffffu, a, 16);
                float tb = __shfl_xor_sync(0xffffffffu, b, 16);
                float v = (lane & 16) ? (b + tb) : (a + ta);
                v += __shfl_xor_sync(0xffffffffu, v, 8);
                v += __shfl_xor_sync(0xffffffffu, v, 4);
                v += __shfl_xor_sync(0xffffffffu, v, 2);
                v += __shfl_xor_sync(0xffffffffu, v, 1);
                if (lane == t)      lo[rp] = v;
                if (lane == 16 + t) hi[rp] = v;
            }
        }

        // Publish quarter-partials: scx[par][sc][tok][q]
        float* sb = scx + par * 256;
        if (lane < T_TOK) {
            #pragma unroll
            for (int rp = 0; rp < 4; rp++)
                sb[((role * 8 + rp) * 4 + lane) * 4 + dq] = lo[rp];
        } else if (lane >= 16 && lane < 16 + T_TOK) {
            const int t = lane - 16;
            #pragma unroll
            for (int rp = 0; rp < 4; rp++)
                sb[((role * 8 + rp + 4) * 4 + t) * 4 + dq] = hi[rp];
        }

        __syncthreads();

        // Warp 0: lanes 0..7 combine quarters and finish. lane = tok*2 + crole.
        if (wid == 0) {
            const int tok  = lane >> 1;      // 0..3 (valid for lane<8)
            const int cr   = lane & 1;       // 0 = group scores, 1 = expert scores
            float s[8];
            #pragma unroll
            for (int k = 0; k < 8; k++) {
                float4 q = *reinterpret_cast<float4*>(
                    sb + ((cr * 8 + k) * 4 + (tok & 3)) * 4);
                s[k] = (q.x + q.y) + (q.z + q.w);
            }

            // top-2 of 8, lax.top_k tie rule (lowest index wins)
            float v1 = s[0]; int i1 = 0;
            #pragma unroll
            for (int k = 1; k < 8; k++) if (s[k] > v1) { v1 = s[k]; i1 = k; }
            float v2 = -3.402823466e+38f; int i2 = 0;
            #pragma unroll
            for (int k = 0; k < 8; k++) if (k != i1 && s[k] > v2) { v2 = s[k]; i2 = k; }

            // exchange with partner lane (other role, same token)
            float p1 = __shfl_xor_sync(0xffffffffu, v1, 1);
            float p2 = __shfl_xor_sync(0xffffffffu, v2, 1);
            int   pid = __shfl_xor_sync(0xffffffffu, i1 * 8 + i2, 1);

            if (lane < 8 && cr == 0) {
                const int g1 = i1, g2 = i2;
                const float g1v = v1, g2v = v2;
                const int e1 = pid >> 3, e2 = pid & 7;
                const float e1v = p1, e2v = p2;

                const float c0 = g1v + e1v;
                const float c1 = g1v + e2v;
                const float c2 = g2v + e1v;
                const float c3 = g2v + e2v;
                const float m  = fmaxf(fmaxf(c0, c1), fmaxf(c2, c3));
                float w0 = __expf(c0 - m);
                float w1 = __expf(c1 - m);
                float w2 = __expf(c2 - m);
                float w3 = __expf(c3 - m);
                const float inv = 1.0f / (w0 + w1 + w2 + w3);
                w0 *= inv; w1 *= inv; w2 *= inv; w3 *= inv;

                const int tokg = tok0 + tok;
                float4 idxv = make_float4((float)(g1 * 8 + e1), (float)(g1 * 8 + e2),
                                          (float)(g2 * 8 + e1), (float)(g2 * 8 + e2));
                float4 wv4  = make_float4(w0, w1, w2, w3);
                *reinterpret_cast<float4*>(out + (size_t)tokg * 4) = idxv;
                *reinterpret_cast<float4*>(out + (size_t)TOKENS * 4 + (size_t)tokg * 4) = wv4;
            }
        }
        // next iteration writes the other parity buffer; its __syncthreads
        // orders those writes after this combine's reads.
    }
}

extern "C" void kernel_launch(void* const* d_in, const int* in_sizes, int n_in,
                              void* d_out, int out_size) {
    const float* x  = (const float*)d_in[0];
    const float* W1 = (const float*)d_in[1];
    const float* W2 = (const float*)d_in[2];
    float* out = (float*)d_out;

    router_kernel<<<GRID, BLOCK>>>(x, W1, W2, out);
}

// round 17
// speedup vs baseline: 1.0161x; 1.0161x over previous
#include <cuda_runtime.h>
#include <cstdint>

#define D_DIM   2048
#define TOKENS  32768
#define T_TOK   4
#define NTILES  (TOKENS / T_TOK)     // 8192 exact
#define BLOCK   256                  // 8 warps: (role 0|1) x (d-quarter 0..3)
#define GRID    152
// score exchange: [parity 2][score 16][tok 4][quarter 4] floats = 2KB
#define SMEM_FLOATS (2 * 16 * 4 * 4)

__device__ __forceinline__ void ffma2(unsigned long long &acc,
                                      unsigned long long a,
                                      unsigned long long b) {
    asm("fma.rn.f32x2 %0, %1, %2, %0;" : "+l"(acc) : "l"(a), "l"(b));
}

// Load one 128-float block of this warp's quarter for T_TOK tokens.
#define LOADX(buf, xq, blk)                                                    \
    {                                                                          \
        _Pragma("unroll")                                                      \
        for (int t = 0; t < T_TOK; t++)                                        \
            buf[t] = *reinterpret_cast<const ulonglong2*>(                     \
                (xq) + (size_t)t * D_DIM + (blk) * 128);                       \
    }

// FMA one block against register-resident W: 8 rows x T_TOK tokens.
#define COMPW(buf, blk)                                                        \
    {                                                                          \
        _Pragma("unroll")                                                      \
        for (int r = 0; r < 8; r++) {                                          \
            _Pragma("unroll")                                                  \
            for (int t = 0; t < T_TOK; t++) {                                  \
                ffma2(acc[r][t], buf[t].x, Wr[r][blk].x);                      \
                ffma2(acc[r][t], buf[t].y, Wr[r][blk].y);                      \
            }                                                                  \
        }                                                                      \
    }

extern "C" __global__ void __launch_bounds__(BLOCK, 1)
router_kernel(const float* __restrict__ x,
              const float* __restrict__ W1,
              const float* __restrict__ W2,
              float* __restrict__ out)
{
    __shared__ float scx[SMEM_FLOATS];

    const int lane = threadIdx.x & 31;
    const int wid  = threadIdx.x >> 5;
    const int role = wid & 1;            // 0 = W1 (group) rows, 1 = W2 (expert) rows
    const int dq   = wid >> 1;           // d-quarter 0..3 (512 floats each)

    // ---- W lives in registers: 8 rows x 4 blocks x float4 per lane (128 regs).
    const float* Wbase = role ? W2 : W1;
    ulonglong2 Wr[8][4];
    #pragma unroll
    for (int r = 0; r < 8; r++)
        #pragma unroll
        for (int b = 0; b < 4; b++)
            Wr[r][b] = *reinterpret_cast<const ulonglong2*>(
                Wbase + r * D_DIM + dq * 512 + b * 128 + lane * 4);

    int tile = blockIdx.x;
    const float* xp = x + (size_t)tile * T_TOK * D_DIM + dq * 512 + lane * 4;

    // prime the x pipeline (blocks 0,1 of tile 0)
    ulonglong2 bA[T_TOK], bB[T_TOK];
    LOADX(bA, xp, 0);
    LOADX(bB, xp, 1);

    int par = 0;
    for (; tile < NTILES; tile += GRID, par ^= 1) {
        const int tok0 = tile * T_TOK;
        // next tile's x base (clamped; duplicate prefetch is harmless)
        const int ntile = (tile + GRID < NTILES) ? (tile + GRID) : tile;
        const float* xn = x + (size_t)ntile * T_TOK * D_DIM + dq * 512 + lane * 4;

        unsigned long long acc[8][T_TOK];
        #pragma unroll
        for (int r = 0; r < 8; r++)
            #pragma unroll
            for (int t = 0; t < T_TOK; t++)
                acc[r][t] = 0ull;

        COMPW(bA, 0); LOADX(bA, xp, 2);
        COMPW(bB, 1); LOADX(bB, xp, 3);
        COMPW(bA, 2); LOADX(bA, xn, 0);   // next-tile prefetch covers reduce phase
        COMPW(bB, 3); LOADX(bB, xn, 1);
        xp = xn;

        // Split-lane reduction over the 32 lanes (this warp's d-quarter):
        // pairs (rp, rp+4); lane t ends with row rp, lane 16+t with row rp+4.
        float lo[4], hi[4];
        #pragma unroll
        for (int rp = 0; rp < 4; rp++) {
            #pragma unroll
            for (int t = 0; t < T_TOK; t++) {
                float2 fa = *reinterpret_cast<float2*>(&acc[rp][t]);
                float2 fb = *reinterpret_cast<float2*>(&acc[rp + 4][t]);
                float a = fa.x + fa.y;
                float b = fb.x + fb.y;
                float ta = __shfl_xor_sync(0xffffffffu, a, 16);
                float tb = __shfl_xor_sync(0xffffffffu, b, 16);
                float v = (lane & 16) ? (b + tb) : (a + ta);
                v += __shfl_xor_sync(0xffffffffu, v, 8);
                v += __shfl_xor_sync(0xffffffffu, v, 4);
                v += __shfl_xor_sync(0xffffffffu, v, 2);
                v += __shfl_xor_sync(0xffffffffu, v, 1);
                if (lane == t)      lo[rp] = v;
                if (lane == 16 + t) hi[rp] = v;
            }
        }

        // Publish quarter-partials: scx[par][sc][tok][q]
        float* sb = scx + par * 256;
        if (lane < T_TOK) {
            #pragma unroll
            for (int rp = 0; rp < 4; rp++)
                sb[((role * 8 + rp) * 4 + lane) * 4 + dq] = lo[rp];
        } else if (lane >= 16 && lane < 16 + T_TOK) {
            const int t = lane - 16;
            #pragma unroll
            for (int rp = 0; rp < 4; rp++)
                sb[((role * 8 + rp + 4) * 4 + t) * 4 + dq] = hi[rp];
        }

        __syncthreads();

        // Warp 0: lanes 0..7 combine quarters and finish. lane = tok*2 + crole.
        if (wid == 0) {
            const int tok  = lane >> 1;      // 0..3 (valid for lane<8)
            const int cr   = lane & 1;       // 0 = group scores, 1 = expert scores
            float s[8];
            #pragma unroll
            for (int k = 0; k < 8; k++) {
                float4 q = *reinterpret_cast<float4*>(
                    sb + ((cr * 8 + k) * 4 + (tok & 3)) * 4);
                s[k] = (q.x + q.y) + (q.z + q.w);
            }

            // top-2 of 8, lax.top_k tie rule (lowest index wins)
            float v1 = s[0]; int i1 = 0;
            #pragma unroll
            for (int k = 1; k < 8; k++) if (s[k] > v1) { v1 = s[k]; i1 = k; }
            float v2 = -3.402823466e+38f; int i2 = 0;
            #pragma unroll
            for (int k = 0; k < 8; k++) if (k != i1 && s[k] > v2) { v2 = s[k]; i2 = k; }

            // exchange with partner lane (other role, same token)
            float p1 = __shfl_xor_sync(0xffffffffu, v1, 1);
            float p2 = __shfl_xor_sync(0xffffffffu, v2, 1);
            int   pid = __shfl_xor_sync(0xffffffffu, i1 * 8 + i2, 1);

            if (lane < 8 && cr == 0) {
                const int g1 = i1, g2 = i2;
                const float g1v = v1, g2v = v2;
                const int e1 = pid >> 3, e2 = pid & 7;
                const float e1v = p1, e2v = p2;

                const float c0 = g1v + e1v;
                const float c1 = g1v + e2v;
                const float c2 = g2v + e1v;
                const float c3 = g2v + e2v;
                const float m  = fmaxf(fmaxf(c0, c1), fmaxf(c2, c3));
                float w0 = __expf(c0 - m);
                float w1 = __expf(c1 - m);
                float w2 = __expf(c2 - m);
                float w3 = __expf(c3 - m);
                const float inv = 1.0f / (w0 + w1 + w2 + w3);
                w0 *= inv; w1 *= inv; w2 *= inv; w3 *= inv;

                const int tokg = tok0 + tok;
                float4 idxv = make_float4((float)(g1 * 8 + e1), (float)(g1 * 8 + e2),
                                          (float)(g2 * 8 + e1), (float)(g2 * 8 + e2));
                float4 wv4  = make_float4(w0, w1, w2, w3);
                *reinterpret_cast<float4*>(out + (size_t)tokg * 4) = idxv;
                *reinterpret_cast<float4*>(out + (size_t)TOKENS * 4 + (size_t)tokg * 4) = wv4;
            }
        }
        // next iteration writes the other parity buffer; its __syncthreads
        // orders those writes after this combine's reads.
    }
}

extern "C" void kernel_launch(void* const* d_in, const int* in_sizes, int n_in,
                              void* d_out, int out_size) {
    const float* x  = (const float*)d_in[0];
    const float* W1 = (const float*)d_in[1];
    const float* W2 = (const float*)d_in[2];
    float* out = (float*)d_out;

    router_kernel<<<GRID, BLOCK>>>(x, W1, W2, out);
}